// round 3
// baseline (speedup 1.0000x reference)
#include <cuda_runtime.h>
#include <cuda_bf16.h>
#include <stdint.h>

// SelectiveLinear: out[b,:] = X[b,:] @ W[idx[b]] + bias[idx[b]]
// B=2048, IN=512, OUT=512, H=16.
// Pipeline: detect idx dtype -> bucket rows by head -> grouped fp32 SGEMM
// (64x64x32 tiles, 4x4 micro-tile) -> echo head indices into output tail.
// (Resubmission of R1 candidate: R2 bench was an infra failure.)

#define IN_DIM  512
#define OUT_DIM 512
#define NHEADS  16
#define MTILE   64
#define NTILE   64
#define KTILE   32
#define MAXB    8192

__device__ int g_rows[MAXB];
__device__ int g_off[NHEADS + 1];
__device__ int g_is64;   // 1 if idx buffer is int64, 0 if int32

// ---------------------------------------------------------------------------
// Kernel 0: sniff index dtype. Reads only the first Bn int32 words (safe for
// both layouts). int64 little-endian pattern: [v0,0,v1,0,...] with v in range.
// ---------------------------------------------------------------------------
__global__ void detect_idx_dtype(const int* __restrict__ idx_w, int Bn) {
    __shared__ int s_notI64;
    if (threadIdx.x == 0) s_notI64 = 0;
    __syncthreads();
    for (int i = threadIdx.x; i < Bn; i += blockDim.x) {
        int v = idx_w[i];
        if (i & 1) {
            if (v != 0) s_notI64 = 1;               // odd word nonzero -> int32
        } else {
            if (v < 0 || v >= NHEADS) s_notI64 = 1; // even word out of range -> int32
        }
    }
    __syncthreads();
    if (threadIdx.x == 0) g_is64 = s_notI64 ? 0 : 1;
}

__device__ __forceinline__ int load_idx(const int* __restrict__ idx_w, int b, int is64) {
    // low 32 bits are sufficient (values 0..15)
    return idx_w[is64 ? (b << 1) : b];
}

// ---------------------------------------------------------------------------
// Kernel A: bucket rows by head (single block).
// ---------------------------------------------------------------------------
__global__ void build_buckets(const int* __restrict__ idx_w, int Bn) {
    __shared__ int s_cnt[NHEADS];
    __shared__ int s_base[NHEADS];
    const int is64 = g_is64;
    int tid = threadIdx.x;
    if (tid < NHEADS) s_cnt[tid] = 0;
    __syncthreads();
    for (int b = tid; b < Bn; b += blockDim.x) {
        int h = load_idx(idx_w, b, is64) & (NHEADS - 1);
        atomicAdd(&s_cnt[h], 1);
    }
    __syncthreads();
    if (tid == 0) {
        int acc = 0;
        for (int h = 0; h < NHEADS; h++) {
            g_off[h]  = acc;
            s_base[h] = acc;
            acc += s_cnt[h];
        }
        g_off[NHEADS] = acc;
    }
    __syncthreads();
    for (int b = tid; b < Bn; b += blockDim.x) {
        int h = load_idx(idx_w, b, is64) & (NHEADS - 1);
        int pos = atomicAdd(&s_base[h], 1);
        g_rows[pos] = b;
    }
}

// ---------------------------------------------------------------------------
// Kernel B: grouped SGEMM.
// grid: (OUT_DIM/NTILE, m_slots, NHEADS); block: 256 threads (16x16).
// ---------------------------------------------------------------------------
__global__ __launch_bounds__(256, 2)
void grouped_sgemm(const float* __restrict__ X,
                   const float* __restrict__ W,
                   const float* __restrict__ bias,
                   float* __restrict__ out) {
    const int h  = blockIdx.z;
    const int n0 = blockIdx.x * NTILE;

    const int m_begin = g_off[h] + blockIdx.y * MTILE;
    const int m_end   = g_off[h + 1];
    if (m_begin >= m_end) return;
    const int nrows = min(MTILE, m_end - m_begin);

    __shared__ float As[MTILE][KTILE + 1];   // [row][k]
    __shared__ float Bs[KTILE][NTILE];       // [k][col]
    __shared__ int   s_rows[MTILE];

    const int tid = threadIdx.x;
    const int tx  = tid & 15;   // 4 output cols each
    const int ty  = tid >> 4;   // 4 output rows each

    if (tid < MTILE) {
        s_rows[tid] = (tid < nrows) ? g_rows[m_begin + tid] : -1;
    }
    __syncthreads();

    int my_b[4];
#pragma unroll
    for (int i = 0; i < 4; i++) my_b[i] = s_rows[ty * 4 + i];

    const float* Wh = W + (size_t)h * IN_DIM * OUT_DIM;

    float acc[4][4];
#pragma unroll
    for (int i = 0; i < 4; i++)
#pragma unroll
        for (int j = 0; j < 4; j++) acc[i][j] = 0.0f;

    const int lane   = tid & 31;          // k index for A loads
    const int arow0  = tid >> 5;          // 0..7, step 8
    const int bc     = tid & 63;          // col for B loads
    const int bk0    = tid >> 6;          // 0..3, step 4

    for (int k0 = 0; k0 < IN_DIM; k0 += KTILE) {
#pragma unroll
        for (int p = 0; p < 8; p++) {
            int r = arow0 + p * 8;
            int b = s_rows[r];
            float v = 0.0f;
            if (b >= 0) v = X[(size_t)b * IN_DIM + k0 + lane];
            As[r][lane] = v;
        }
#pragma unroll
        for (int p = 0; p < 8; p++) {
            int kk = bk0 + p * 4;
            Bs[kk][bc] = Wh[(size_t)(k0 + kk) * OUT_DIM + n0 + bc];
        }
        __syncthreads();

#pragma unroll
        for (int k = 0; k < KTILE; k++) {
            float a0 = As[ty * 4 + 0][k];
            float a1 = As[ty * 4 + 1][k];
            float a2 = As[ty * 4 + 2][k];
            float a3 = As[ty * 4 + 3][k];
            float4 bv = *(const float4*)&Bs[k][tx * 4];
            acc[0][0] += a0 * bv.x; acc[0][1] += a0 * bv.y;
            acc[0][2] += a0 * bv.z; acc[0][3] += a0 * bv.w;
            acc[1][0] += a1 * bv.x; acc[1][1] += a1 * bv.y;
            acc[1][2] += a1 * bv.z; acc[1][3] += a1 * bv.w;
            acc[2][0] += a2 * bv.x; acc[2][1] += a2 * bv.y;
            acc[2][2] += a2 * bv.z; acc[2][3] += a2 * bv.w;
            acc[3][0] += a3 * bv.x; acc[3][1] += a3 * bv.y;
            acc[3][2] += a3 * bv.z; acc[3][3] += a3 * bv.w;
        }
        __syncthreads();
    }

    float4 bias4 = *(const float4*)&bias[h * OUT_DIM + n0 + tx * 4];
#pragma unroll
    for (int i = 0; i < 4; i++) {
        int b = my_b[i];
        if (b < 0) continue;
        float4 r;
        r.x = acc[i][0] + bias4.x;
        r.y = acc[i][1] + bias4.y;
        r.z = acc[i][2] + bias4.z;
        r.w = acc[i][3] + bias4.w;
        *(float4*)&out[(size_t)b * OUT_DIM + n0 + tx * 4] = r;
    }
}

// ---------------------------------------------------------------------------
// Kernel C: echo head indices into the tail of the output buffer.
// mode 1: tail is Bn floats (idx cast to float)
// mode 2: tail is Bn int64-sized slots (raw int64 values)
// ---------------------------------------------------------------------------
__global__ void write_tail(const int* __restrict__ idx_w, int Bn,
                           float* __restrict__ tail, int mode) {
    const int is64 = g_is64;
    int b = blockIdx.x * blockDim.x + threadIdx.x;
    if (b >= Bn) return;
    int v = load_idx(idx_w, b, is64) & (NHEADS - 1);
    if (mode == 1) {
        tail[b] = (float)v;
    } else {
        ((long long*)tail)[b] = (long long)v;
    }
}

extern "C" void kernel_launch(void* const* d_in, const int* in_sizes, int n_in,
                              void* d_out, int out_size) {
    const float* X     = (const float*)d_in[0];
    const int*   idx_w = (const int*)d_in[1];   // int32 view; dtype sniffed on device
    const float* W     = (const float*)d_in[2];
    const float* bias  = (const float*)d_in[3];
    float*       out   = (float*)d_out;

    const int Bn = in_sizes[1];  // element count of the index array

    detect_idx_dtype<<<1, 256>>>(idx_w, Bn);
    build_buckets<<<1, 256>>>(idx_w, Bn);

    int m_slots = (Bn + MTILE - 1) / MTILE;   // worst case: all rows one head
    dim3 grid(OUT_DIM / NTILE, m_slots, NHEADS);
    grouped_sgemm<<<grid, 256>>>(X, W, bias, out);

    long long extra = (long long)out_size - (long long)Bn * OUT_DIM;
    if (extra >= Bn) {
        int mode = (extra >= 2 * (long long)Bn) ? 2 : 1;
        write_tail<<<(Bn + 255) / 256, 256>>>(idx_w, Bn, out + (size_t)Bn * OUT_DIM, mode);
    }
}

// round 6
// speedup vs baseline: 1.1004x; 1.1004x over previous
#include <cuda_runtime.h>
#include <cuda_bf16.h>
#include <stdint.h>

// SelectiveLinear: out[b,:] = X[b,:] @ W[idx[b]] + bias[idx[b]]
// B=2048, IN=512, OUT=512, H=16.
// R6 = resubmission of R5 (bench infra failed twice; no kernel evidence).
// Harness PTX target is plain sm_100 (no tcgen05), so use classic
// mma.sync (HMMA) bf16 with 3-term split-fp32 emulation:
//   out = Xhi*Whi + Xlo*Whi + Xhi*Wlo   (fp32 accum, rel_err ~1e-6)

#define IN_DIM  512
#define OUT_DIM 512
#define NHEADS  16
#define MAXB    2048
#define KPACK   1024            // g_A row: [hi(512) | lo(512)] bf16
#define NCHUNK  48              // 3 terms x 16 chunks of 32 k
#define A_STRIDE_B 80           // A smem row stride bytes (64B data + pad)
#define B_STRIDE_B 272          // B smem row stride bytes (256B data + pad)
#define A_TILE_B  (128 * A_STRIDE_B)   // 10240
#define B_TILE_B  (32 * B_STRIDE_B)    // 8704
#define STAGE_B   (A_TILE_B + B_TILE_B)

__device__ int g_rows[MAXB];
__device__ int g_off[NHEADS + 1];
__device__ int g_is64;
__device__ __align__(256) __nv_bfloat16 g_A[(size_t)MAXB * KPACK];            // 4MB
__device__ __align__(256) __nv_bfloat16 g_Bw[(size_t)NHEADS * 2 * IN_DIM * OUT_DIM]; // 16MB [h][sel][k][n]

__device__ __forceinline__ uint32_t smem_u32(const void* p) {
    uint32_t a;
    asm("{ .reg .u64 t; cvta.to.shared.u64 t, %1; cvt.u32.u64 %0, t; }"
        : "=r"(a) : "l"(p));
    return a;
}
__device__ __forceinline__ void cpasync16(uint32_t dst, const void* src) {
    asm volatile("cp.async.cg.shared.global [%0], [%1], 16;" :: "r"(dst), "l"(src) : "memory");
}
#define CP_COMMIT() asm volatile("cp.async.commit_group;" ::: "memory")
#define CP_WAIT1()  asm volatile("cp.async.wait_group 1;" ::: "memory")

// ---------------------------------------------------------------------------
// Kernel 0: sniff index dtype (int64 LE pattern: [v,0,v,0,...], v in range).
// ---------------------------------------------------------------------------
__global__ void detect_idx_dtype(const int* __restrict__ idx_w, int Bn) {
    __shared__ int s_not;
    if (threadIdx.x == 0) s_not = 0;
    __syncthreads();
    for (int i = threadIdx.x; i < Bn; i += blockDim.x) {
        int v = idx_w[i];
        if (i & 1) { if (v != 0) s_not = 1; }
        else       { if (v < 0 || v >= NHEADS) s_not = 1; }
    }
    __syncthreads();
    if (threadIdx.x == 0) g_is64 = s_not ? 0 : 1;
}
__device__ __forceinline__ int load_idx(const int* __restrict__ w, int b, int is64) {
    return w[is64 ? (b << 1) : b];
}

// ---------------------------------------------------------------------------
// Kernel A: bucket rows by head.
// ---------------------------------------------------------------------------
__global__ void build_buckets(const int* __restrict__ idx_w, int Bn) {
    __shared__ int s_cnt[NHEADS];
    __shared__ int s_base[NHEADS];
    const int is64 = g_is64;
    int tid = threadIdx.x;
    if (tid < NHEADS) s_cnt[tid] = 0;
    __syncthreads();
    for (int b = tid; b < Bn; b += blockDim.x)
        atomicAdd(&s_cnt[load_idx(idx_w, b, is64) & (NHEADS - 1)], 1);
    __syncthreads();
    if (tid == 0) {
        int acc = 0;
        for (int h = 0; h < NHEADS; h++) { g_off[h] = acc; s_base[h] = acc; acc += s_cnt[h]; }
        g_off[NHEADS] = acc;
    }
    __syncthreads();
    for (int b = tid; b < Bn; b += blockDim.x) {
        int h = load_idx(idx_w, b, is64) & (NHEADS - 1);
        g_rows[atomicAdd(&s_base[h], 1)] = b;
    }
}

// ---------------------------------------------------------------------------
// Kernel B: convert X -> g_A[p][0:512]=hi, [512:1024]=lo (sorted order).
// ---------------------------------------------------------------------------
__global__ void convert_X(const float* __restrict__ X, int Bn) {
    int p = blockIdx.x * 8 + (threadIdx.x >> 5);
    int l = threadIdx.x & 31;
    if (p >= Bn) return;
    int b = g_rows[p];
    const float4* xr = (const float4*)(X + (size_t)b * IN_DIM);
    union { __nv_bfloat16 h[16]; uint4 u[2]; } hi, lo;
#pragma unroll
    for (int q = 0; q < 4; q++) {
        float4 v = xr[l * 4 + q];
        float f[4] = {v.x, v.y, v.z, v.w};
#pragma unroll
        for (int e = 0; e < 4; e++) {
            __nv_bfloat16 hv = __float2bfloat16(f[e]);
            hi.h[q * 4 + e] = hv;
            lo.h[q * 4 + e] = __float2bfloat16(f[e] - __bfloat162float(hv));
        }
    }
    uint4* dh = (uint4*)(g_A + (size_t)p * KPACK + l * 16);
    dh[0] = hi.u[0]; dh[1] = hi.u[1];
    uint4* dl = (uint4*)(g_A + (size_t)p * KPACK + 512 + l * 16);
    dl[0] = lo.u[0]; dl[1] = lo.u[1];
}

// ---------------------------------------------------------------------------
// Kernel C: elementwise split W[h][k][n] -> g_Bw[h][0][k][n]=hi, [h][1][k][n]=lo.
// ---------------------------------------------------------------------------
__global__ void convert_W(const float* __restrict__ W) {
    int id = blockIdx.x * blockDim.x + threadIdx.x;   // over 16*512*128 float4s
    if (id >= NHEADS * IN_DIM * (OUT_DIM / 4)) return;
    int h   = id / (IN_DIM * (OUT_DIM / 4));
    int rem = id % (IN_DIM * (OUT_DIM / 4));
    int k   = rem / (OUT_DIM / 4);
    int n4  = rem % (OUT_DIM / 4);
    float4 v = ((const float4*)W)[(size_t)id];
    float f[4] = {v.x, v.y, v.z, v.w};
    union { __nv_bfloat16 h[4]; uint2 u; } hi, lo;
#pragma unroll
    for (int e = 0; e < 4; e++) {
        __nv_bfloat16 hv = __float2bfloat16(f[e]);
        hi.h[e] = hv;
        lo.h[e] = __float2bfloat16(f[e] - __bfloat162float(hv));
    }
    size_t basehi = (((size_t)h * 2 + 0) * IN_DIM + k) * OUT_DIM + n4 * 4;
    size_t baselo = (((size_t)h * 2 + 1) * IN_DIM + k) * OUT_DIM + n4 * 4;
    *(uint2*)(g_Bw + basehi) = hi.u;
    *(uint2*)(g_Bw + baselo) = lo.u;
}

// ---------------------------------------------------------------------------
// Kernel D: grouped GEMM via mma.sync bf16 (HMMA).
// grid (4 n-tiles, m_slots, 16 heads), 256 threads (8 warps, 4m x 2n).
// Block tile M=128, N=128; warp tile 32x64; K: 48 chunks of 32 bf16.
// ---------------------------------------------------------------------------
__global__ __launch_bounds__(256)
void gemm_mma(const float* __restrict__ bias, float* __restrict__ out, int Bn) {
    const int h  = blockIdx.z;
    const int n0 = blockIdx.x * 128;
    const int m_begin = g_off[h] + blockIdx.y * 128;
    const int m_end   = g_off[h + 1];
    if (m_begin >= m_end) return;

    __shared__ __align__(16) char sm[2][STAGE_B];

    const int tid  = threadIdx.x;
    const int lane = tid & 31;
    const int wid  = tid >> 5;
    const int wm   = wid & 3;          // 4 warps over M
    const int wn   = wid >> 2;         // 2 warps over N

    float acc[2][8][4];
#pragma unroll
    for (int mi = 0; mi < 2; mi++)
#pragma unroll
        for (int ni = 0; ni < 8; ni++)
#pragma unroll
            for (int e = 0; e < 4; e++) acc[mi][ni][e] = 0.0f;

    // Per-thread load coordinates (fixed across chunks)
    const int arow = tid >> 2, aseg = tid & 3;       // +i*256: rows 0..63 / 64..127
    const int brow = tid >> 4, bseg = tid & 15;      // +i*256: rows 0..15 / 16..31

    // precompute clamped gathered row pointers for A (2 rows per thread)
    const __nv_bfloat16* aSrc[2];
#pragma unroll
    for (int i = 0; i < 2; i++) {
        int r = arow + i * 64;
        int p = m_begin + r;
        if (p > Bn - 1) p = Bn - 1;
        aSrc[i] = g_A + (size_t)p * KPACK + aseg * 8;
    }

    auto load_chunk = [&](int c, int stg) {
        const int t  = c >> 4;               // term 0,1,2
        const int kk = (c & 15) << 5;        // k offset in 0..480
        const int Acol = ((t == 1) ? 512 : 0) + kk;
        const int Bsel = (t == 2) ? 1 : 0;
        const uint32_t aB = smem_u32(&sm[stg][0]);
        const uint32_t bB = aB + A_TILE_B;
#pragma unroll
        for (int i = 0; i < 2; i++) {
            int r = arow + i * 64;
            cpasync16(aB + r * A_STRIDE_B + aseg * 16, aSrc[i] + Acol);
        }
        const __nv_bfloat16* bsrc =
            g_Bw + (((size_t)h * 2 + Bsel) * IN_DIM + kk) * OUT_DIM + n0 + bseg * 8;
#pragma unroll
        for (int i = 0; i < 2; i++) {
            int r = brow + i * 16;
            cpasync16(bB + r * B_STRIDE_B + bseg * 16,
                      bsrc + (size_t)r * OUT_DIM);
        }
        CP_COMMIT();
    };

    load_chunk(0, 0);
    load_chunk(1, 1);

    for (int c = 0; c < NCHUNK; c++) {
        CP_WAIT1();
        __syncthreads();

        const int stg = c & 1;
        const uint32_t aB = smem_u32(&sm[stg][0]);
        const uint32_t bB = aB + A_TILE_B;

#pragma unroll
        for (int km = 0; km < 32; km += 16) {
            // A fragments: 2 x (m16 x k16)
            uint32_t a[2][4];
#pragma unroll
            for (int mi = 0; mi < 2; mi++) {
                int row = wm * 32 + mi * 16 + (lane & 15);
                uint32_t addr = aB + row * A_STRIDE_B + km * 2 + ((lane >> 4) & 1) * 16;
                asm volatile("ldmatrix.sync.aligned.m8n8.x4.shared.b16 {%0,%1,%2,%3}, [%4];"
                    : "=r"(a[mi][0]), "=r"(a[mi][1]), "=r"(a[mi][2]), "=r"(a[mi][3])
                    : "r"(addr));
            }
            // B fragments: 8 x (k16 x n8) via 4 x ldmatrix.x4.trans (n16 each)
            uint32_t b[8][2];
#pragma unroll
            for (int g = 0; g < 4; g++) {
                int krow = km + (lane & 7) + ((lane >> 3) & 1) * 8;
                int ncol = wn * 64 + g * 16 + ((lane >> 4) & 1) * 8;
                uint32_t addr = bB + krow * B_STRIDE_B + ncol * 2;
                asm volatile("ldmatrix.sync.aligned.m8n8.x4.trans.shared.b16 {%0,%1,%2,%3}, [%4];"
                    : "=r"(b[g * 2][0]), "=r"(b[g * 2][1]),
                      "=r"(b[g * 2 + 1][0]), "=r"(b[g * 2 + 1][1])
                    : "r"(addr));
            }
#pragma unroll
            for (int mi = 0; mi < 2; mi++)
#pragma unroll
                for (int ni = 0; ni < 8; ni++) {
                    asm volatile(
                        "mma.sync.aligned.m16n8k16.row.col.f32.bf16.bf16.f32 "
                        "{%0,%1,%2,%3}, {%4,%5,%6,%7}, {%8,%9}, {%0,%1,%2,%3};"
                        : "+f"(acc[mi][ni][0]), "+f"(acc[mi][ni][1]),
                          "+f"(acc[mi][ni][2]), "+f"(acc[mi][ni][3])
                        : "r"(a[mi][0]), "r"(a[mi][1]), "r"(a[mi][2]), "r"(a[mi][3]),
                          "r"(b[ni][0]), "r"(b[ni][1]));
                }
        }
        __syncthreads();
        if (c + 2 < NCHUNK) load_chunk(c + 2, stg);
    }

    // Epilogue: acc[mi][ni][e]: row = wm*32+mi*16+(e>=2?8:0)+(lane>>2),
    //           col = wn*64+ni*8+(lane&3)*2+(e&1)
#pragma unroll
    for (int mi = 0; mi < 2; mi++) {
#pragma unroll
        for (int rp = 0; rp < 2; rp++) {
            int r = wm * 32 + mi * 16 + rp * 8 + (lane >> 2);
            int p = m_begin + r;
            if (p < m_end) {
                int bb = g_rows[p];
                float* op = out + (size_t)bb * OUT_DIM + n0 + wn * 64 + (lane & 3) * 2;
                const float* bp = bias + h * OUT_DIM + n0 + wn * 64 + (lane & 3) * 2;
#pragma unroll
                for (int ni = 0; ni < 8; ni++) {
                    float2 r2;
                    r2.x = acc[mi][ni][rp * 2 + 0] + bp[ni * 8 + 0];
                    r2.y = acc[mi][ni][rp * 2 + 1] + bp[ni * 8 + 1];
                    *(float2*)(op + ni * 8) = r2;
                }
            }
        }
    }
}

// ---------------------------------------------------------------------------
// Kernel E: echo head indices into the output tail.
// ---------------------------------------------------------------------------
__global__ void write_tail(const int* __restrict__ idx_w, int Bn,
                           float* __restrict__ tail, int mode) {
    const int is64 = g_is64;
    int b = blockIdx.x * blockDim.x + threadIdx.x;
    if (b >= Bn) return;
    int v = load_idx(idx_w, b, is64) & (NHEADS - 1);
    if (mode == 1) tail[b] = (float)v;
    else           ((long long*)tail)[b] = (long long)v;
}

extern "C" void kernel_launch(void* const* d_in, const int* in_sizes, int n_in,
                              void* d_out, int out_size) {
    const float* X     = (const float*)d_in[0];
    const int*   idx_w = (const int*)d_in[1];
    const float* W     = (const float*)d_in[2];
    const float* bias  = (const float*)d_in[3];
    float*       out   = (float*)d_out;

    const int Bn = in_sizes[1];

    detect_idx_dtype<<<1, 256>>>(idx_w, Bn);
    build_buckets<<<1, 256>>>(idx_w, Bn);
    convert_X<<<(Bn + 7) / 8, 256>>>(X, Bn);
    {
        int total = NHEADS * IN_DIM * (OUT_DIM / 4);
        convert_W<<<(total + 255) / 256, 256>>>(W);
    }
    {
        int m_slots = (Bn + 127) / 128;
        dim3 g(OUT_DIM / 128, m_slots, NHEADS);
        gemm_mma<<<g, 256>>>(bias, out, Bn);
    }
    long long extra = (long long)out_size - (long long)Bn * OUT_DIM;
    if (extra >= Bn) {
        int mode = (extra >= 2 * (long long)Bn) ? 2 : 1;
        write_tail<<<(Bn + 255) / 256, 256>>>(idx_w, Bn, out + (size_t)Bn * OUT_DIM, mode);
    }
}

// round 9
// speedup vs baseline: 1.2777x; 1.1611x over previous
#include <cuda_runtime.h>
#include <cuda_bf16.h>
#include <stdint.h>

// SelectiveLinear: out[b,:] = X[b,:] @ W[idx[b]] + bias[idx[b]]
// B=2048, IN=512, OUT=512, H=16.
// R9: de-risked variant. Keeps R7's launch fusion (2 launches total) but
// reverts the GEMM mainloop to R6's proven 2-stage STATIC-shared pipeline:
// no dynamic smem, no cudaFuncSetAttribute, no launch_bounds reg cap
// (suspected container-killers in R7/R8).
//   prep: [block 0] idx dtype sniff + bucket-by-head
//         [blocks 1..XB] X -> bf16 hi|lo (stored at original row)
//         [rest]         W -> bf16 hi|lo  [h][sel][k][n]
//   gemm: grouped HMMA split-bf16 (Xhi*Whi + Xlo*Whi + Xhi*Wlo) + tail echo.

#define IN_DIM  512
#define OUT_DIM 512
#define NHEADS  16
#define MAXB    2048
#define KPACK   1024            // g_A row: [hi(512) | lo(512)] bf16
#define NCHUNK  48              // 3 terms x 16 chunks of 32 k
#define A_STRIDE_B 80           // A smem row stride bytes (64B data + 16B pad)
#define B_STRIDE_B 272          // B smem row stride bytes (256B data + 16B pad)
#define A_TILE_B  (128 * A_STRIDE_B)   // 10240
#define B_TILE_B  (32 * B_STRIDE_B)    // 8704
#define STAGE_B   (A_TILE_B + B_TILE_B) // 18944 -> 2 stages = 37888 (static OK)

__device__ int g_rows[MAXB];
__device__ int g_off[NHEADS + 1];
__device__ int g_is64;
__device__ __align__(256) __nv_bfloat16 g_A[(size_t)MAXB * KPACK];                   // 4MB
__device__ __align__(256) __nv_bfloat16 g_Bw[(size_t)NHEADS * 2 * IN_DIM * OUT_DIM]; // 16MB

__device__ __forceinline__ uint32_t smem_u32(const void* p) {
    uint32_t a;
    asm("{ .reg .u64 t; cvta.to.shared.u64 t, %1; cvt.u32.u64 %0, t; }"
        : "=r"(a) : "l"(p));
    return a;
}
__device__ __forceinline__ void cpasync16(uint32_t dst, const void* src) {
    asm volatile("cp.async.cg.shared.global [%0], [%1], 16;" :: "r"(dst), "l"(src) : "memory");
}
#define CP_COMMIT() asm volatile("cp.async.commit_group;" ::: "memory")
#define CP_WAIT1()  asm volatile("cp.async.wait_group 1;" ::: "memory")

__device__ __forceinline__ int load_idx(const int* __restrict__ w, int b, int is64) {
    return w[is64 ? (b << 1) : b];
}

// ---------------------------------------------------------------------------
// Kernel 1: prep — dtype sniff + bucket (block 0), X split (next XB blocks),
// W split (remaining 512 blocks).
// ---------------------------------------------------------------------------
__global__ __launch_bounds__(256)
void prep(const float* __restrict__ X, const int* __restrict__ idx_w,
          const float* __restrict__ W, int Bn) {
    const int bx = blockIdx.x;
    const int tid = threadIdx.x;
    const int XB = (Bn + 7) / 8;

    if (bx == 0) {
        __shared__ int s_not;
        __shared__ int s_cnt[NHEADS];
        __shared__ int s_base[NHEADS];
        if (tid == 0) s_not = 0;
        __syncthreads();
        for (int i = tid; i < Bn; i += 256) {
            int v = idx_w[i];
            if (i & 1) { if (v != 0) s_not = 1; }
            else       { if (v < 0 || v >= NHEADS) s_not = 1; }
        }
        __syncthreads();
        const int is64 = s_not ? 0 : 1;
        if (tid == 0) g_is64 = is64;
        if (tid < NHEADS) s_cnt[tid] = 0;
        __syncthreads();
        for (int b = tid; b < Bn; b += 256)
            atomicAdd(&s_cnt[load_idx(idx_w, b, is64) & (NHEADS - 1)], 1);
        __syncthreads();
        if (tid == 0) {
            int acc = 0;
            for (int h = 0; h < NHEADS; h++) { g_off[h] = acc; s_base[h] = acc; acc += s_cnt[h]; }
            g_off[NHEADS] = acc;
        }
        __syncthreads();
        for (int b = tid; b < Bn; b += 256) {
            int h = load_idx(idx_w, b, is64) & (NHEADS - 1);
            g_rows[atomicAdd(&s_base[h], 1)] = b;
        }
    } else if (bx <= XB) {
        // X split: row p (original index), warp per row
        int p = (bx - 1) * 8 + (tid >> 5);
        int l = tid & 31;
        if (p >= Bn) return;
        const float4* xr = (const float4*)(X + (size_t)p * IN_DIM);
        union { __nv_bfloat16 h[16]; uint4 u[2]; } hi, lo;
#pragma unroll
        for (int q = 0; q < 4; q++) {
            float4 v = xr[l * 4 + q];
            float f[4] = {v.x, v.y, v.z, v.w};
#pragma unroll
            for (int e = 0; e < 4; e++) {
                __nv_bfloat16 hv = __float2bfloat16(f[e]);
                hi.h[q * 4 + e] = hv;
                lo.h[q * 4 + e] = __float2bfloat16(f[e] - __bfloat162float(hv));
            }
        }
        uint4* dh = (uint4*)(g_A + (size_t)p * KPACK + l * 16);
        dh[0] = hi.u[0]; dh[1] = hi.u[1];
        uint4* dl = (uint4*)(g_A + (size_t)p * KPACK + 512 + l * 16);
        dl[0] = lo.u[0]; dl[1] = lo.u[1];
    } else {
        // W split: 512 blocks x 2048 float4s each
        const int wb = bx - 1 - XB;
        const int total = NHEADS * IN_DIM * (OUT_DIM / 4);
#pragma unroll
        for (int i = 0; i < 8; i++) {
            int id = wb * 2048 + i * 256 + tid;
            if (id >= total) break;
            int h   = id / (IN_DIM * (OUT_DIM / 4));
            int rem = id % (IN_DIM * (OUT_DIM / 4));
            int k   = rem / (OUT_DIM / 4);
            int n4  = rem % (OUT_DIM / 4);
            float4 v = ((const float4*)W)[(size_t)id];
            float f[4] = {v.x, v.y, v.z, v.w};
            union { __nv_bfloat16 h[4]; uint2 u; } hi, lo;
#pragma unroll
            for (int e = 0; e < 4; e++) {
                __nv_bfloat16 hv = __float2bfloat16(f[e]);
                hi.h[e] = hv;
                lo.h[e] = __float2bfloat16(f[e] - __bfloat162float(hv));
            }
            size_t basehi = (((size_t)h * 2 + 0) * IN_DIM + k) * OUT_DIM + n4 * 4;
            size_t baselo = (((size_t)h * 2 + 1) * IN_DIM + k) * OUT_DIM + n4 * 4;
            *(uint2*)(g_Bw + basehi) = hi.u;
            *(uint2*)(g_Bw + baselo) = lo.u;
        }
    }
}

// ---------------------------------------------------------------------------
// Kernel 2: grouped GEMM via mma.sync bf16 + fused tail echo.
// grid (4 n-tiles, m_slots, NHEADS+1), 256 threads (8 warps, 4m x 2n).
// Block tile M=128, N=128; warp tile 32x64; K: 48 chunks of 32 bf16;
// 2-stage cp.async pipeline, STATIC shared memory (R6-proven mainloop).
// ---------------------------------------------------------------------------
__global__ __launch_bounds__(256)
void gemm_mma(const float* __restrict__ bias, float* __restrict__ out, int Bn,
              const int* __restrict__ idx_w, float* __restrict__ tail, int mode) {
    // Fused tail block
    if (blockIdx.z == NHEADS) {
        if (blockIdx.x == 0 && blockIdx.y == 0 && tail != nullptr) {
            const int is64 = g_is64;
            for (int b = threadIdx.x; b < Bn; b += 256) {
                int v = load_idx(idx_w, b, is64) & (NHEADS - 1);
                if (mode == 1) tail[b] = (float)v;
                else           ((long long*)tail)[b] = (long long)v;
            }
        }
        return;
    }

    const int h  = blockIdx.z;
    const int n0 = blockIdx.x * 128;
    const int m_begin = g_off[h] + blockIdx.y * 128;
    const int m_end   = g_off[h + 1];
    if (m_begin >= m_end) return;

    __shared__ __align__(16) char sm[2][STAGE_B];

    const int tid  = threadIdx.x;
    const int lane = tid & 31;
    const int wid  = tid >> 5;
    const int wm   = wid & 3;          // 4 warps over M
    const int wn   = wid >> 2;         // 2 warps over N

    float acc[2][8][4];
#pragma unroll
    for (int mi = 0; mi < 2; mi++)
#pragma unroll
        for (int ni = 0; ni < 8; ni++)
#pragma unroll
            for (int e = 0; e < 4; e++) acc[mi][ni][e] = 0.0f;

    // Per-thread load coordinates (fixed across chunks)
    const int arow = tid >> 2, aseg = tid & 3;       // A: rows 0..63 / 64..127
    const int brow = tid >> 4, bseg = tid & 15;      // B: rows 0..15 / 16..31

    // Gathered A row pointers (g_A is unsorted; indirect through g_rows)
    const __nv_bfloat16* aSrc[2];
#pragma unroll
    for (int i = 0; i < 2; i++) {
        int r = arow + i * 64;
        int p = m_begin + r;
        if (p > Bn - 1) p = Bn - 1;
        int b = g_rows[p];
        aSrc[i] = g_A + (size_t)b * KPACK + aseg * 8;
    }

    auto load_chunk = [&](int c, int stg) {
        const int t  = c >> 4;               // term 0,1,2
        const int kk = (c & 15) << 5;        // k offset 0..480
        const int Acol = ((t == 1) ? 512 : 0) + kk;
        const int Bsel = (t == 2) ? 1 : 0;
        const uint32_t aB = smem_u32(&sm[stg][0]);
        const uint32_t bB = aB + A_TILE_B;
#pragma unroll
        for (int i = 0; i < 2; i++) {
            int r = arow + i * 64;
            cpasync16(aB + r * A_STRIDE_B + aseg * 16, aSrc[i] + Acol);
        }
        const __nv_bfloat16* bsrc =
            g_Bw + (((size_t)h * 2 + Bsel) * IN_DIM + kk) * OUT_DIM + n0 + bseg * 8;
#pragma unroll
        for (int i = 0; i < 2; i++) {
            int r = brow + i * 16;
            cpasync16(bB + r * B_STRIDE_B + bseg * 16, bsrc + (size_t)r * OUT_DIM);
        }
        CP_COMMIT();
    };

    load_chunk(0, 0);
    load_chunk(1, 1);

    for (int c = 0; c < NCHUNK; c++) {
        CP_WAIT1();
        __syncthreads();

        const int stg = c & 1;
        const uint32_t aB = smem_u32(&sm[stg][0]);
        const uint32_t bB = aB + A_TILE_B;

#pragma unroll
        for (int km = 0; km < 32; km += 16) {
            uint32_t a[2][4];
#pragma unroll
            for (int mi = 0; mi < 2; mi++) {
                int row = wm * 32 + mi * 16 + (lane & 15);
                uint32_t addr = aB + row * A_STRIDE_B + km * 2 + ((lane >> 4) & 1) * 16;
                asm volatile("ldmatrix.sync.aligned.m8n8.x4.shared.b16 {%0,%1,%2,%3}, [%4];"
                    : "=r"(a[mi][0]), "=r"(a[mi][1]), "=r"(a[mi][2]), "=r"(a[mi][3])
                    : "r"(addr));
            }
            uint32_t b[8][2];
#pragma unroll
            for (int g = 0; g < 4; g++) {
                int krow = km + (lane & 7) + ((lane >> 3) & 1) * 8;
                int ncol = wn * 64 + g * 16 + ((lane >> 4) & 1) * 8;
                uint32_t addr = bB + krow * B_STRIDE_B + ncol * 2;
                asm volatile("ldmatrix.sync.aligned.m8n8.x4.trans.shared.b16 {%0,%1,%2,%3}, [%4];"
                    : "=r"(b[g * 2][0]), "=r"(b[g * 2][1]),
                      "=r"(b[g * 2 + 1][0]), "=r"(b[g * 2 + 1][1])
                    : "r"(addr));
            }
#pragma unroll
            for (int mi = 0; mi < 2; mi++)
#pragma unroll
                for (int ni = 0; ni < 8; ni++) {
                    asm volatile(
                        "mma.sync.aligned.m16n8k16.row.col.f32.bf16.bf16.f32 "
                        "{%0,%1,%2,%3}, {%4,%5,%6,%7}, {%8,%9}, {%0,%1,%2,%3};"
                        : "+f"(acc[mi][ni][0]), "+f"(acc[mi][ni][1]),
                          "+f"(acc[mi][ni][2]), "+f"(acc[mi][ni][3])
                        : "r"(a[mi][0]), "r"(a[mi][1]), "r"(a[mi][2]), "r"(a[mi][3]),
                          "r"(b[ni][0]), "r"(b[ni][1]));
                }
        }
        __syncthreads();
        if (c + 2 < NCHUNK) load_chunk(c + 2, stg);
    }

    // Epilogue: row = wm*32+mi*16+rp*8+(lane>>2), col = wn*64+ni*8+(lane&3)*2
#pragma unroll
    for (int mi = 0; mi < 2; mi++) {
#pragma unroll
        for (int rp = 0; rp < 2; rp++) {
            int r = wm * 32 + mi * 16 + rp * 8 + (lane >> 2);
            int p = m_begin + r;
            if (p < m_end) {
                int bb = g_rows[p];
                float* op = out + (size_t)bb * OUT_DIM + n0 + wn * 64 + (lane & 3) * 2;
                const float* bp = bias + h * OUT_DIM + n0 + wn * 64 + (lane & 3) * 2;
#pragma unroll
                for (int ni = 0; ni < 8; ni++) {
                    float2 r2;
                    r2.x = acc[mi][ni][rp * 2 + 0] + bp[ni * 8 + 0];
                    r2.y = acc[mi][ni][rp * 2 + 1] + bp[ni * 8 + 1];
                    *(float2*)(op + ni * 8) = r2;
                }
            }
        }
    }
}

extern "C" void kernel_launch(void* const* d_in, const int* in_sizes, int n_in,
                              void* d_out, int out_size) {
    const float* X     = (const float*)d_in[0];
    const int*   idx_w = (const int*)d_in[1];
    const float* W     = (const float*)d_in[2];
    const float* bias  = (const float*)d_in[3];
    float*       out   = (float*)d_out;

    const int Bn = in_sizes[1];

    const int XB = (Bn + 7) / 8;
    prep<<<1 + XB + 512, 256>>>(X, idx_w, W, Bn);

    long long extra = (long long)out_size - (long long)Bn * OUT_DIM;
    float* tail = nullptr;
    int mode = 0;
    if (extra >= Bn) {
        mode = (extra >= 2 * (long long)Bn) ? 2 : 1;
        tail = out + (size_t)Bn * OUT_DIM;
    }

    int m_slots = (Bn + 127) / 128;
    dim3 g(OUT_DIM / 128, m_slots, NHEADS + 1);
    gemm_mma<<<g, 256>>>(bias, out, Bn, idx_w, tail, mode);
}

// round 10
// speedup vs baseline: 2.0526x; 1.6064x over previous
#include <cuda_runtime.h>
#include <cuda_bf16.h>
#include <stdint.h>

// SelectiveLinear: out[b,:] = X[b,:] @ W[idx[b]] + bias[idx[b]]
// B=2048, IN=512, OUT=512, H=16.
// R10: occupancy attack. R9 evidence: gemm 57us, occ 16%, tensor 14% -> only
// ~64 working blocks. This round: M-tile 64 (2 m-slots/head), split-K over the
// 3 bf16 terms (independent GEMMs, atomicAdd reduction), 3-stage pipeline with
// corrected tail drain. ~384 working blocks. out zeroed in prep (replay-safe).

#define IN_DIM  512
#define OUT_DIM 512
#define NHEADS  16
#define MAXB    2048
#define KPACK   1024            // g_A row: [hi(512) | lo(512)] bf16
#define NCHUNK_T 16             // chunks per term (each 32 k)
#define A_STRIDE_B 80           // A smem row stride bytes (64B data + 16B pad)
#define B_STRIDE_B 272          // B smem row stride bytes (256B data + 16B pad)
#define A_TILE_B  (64 * A_STRIDE_B)    // 5120
#define B_TILE_B  (32 * B_STRIDE_B)    // 8704
#define STAGE_B   (A_TILE_B + B_TILE_B) // 13824; 3 stages = 41472 (static OK)

__device__ int g_rows[MAXB];
__device__ int g_off[NHEADS + 1];
__device__ int g_is64;
__device__ __align__(256) __nv_bfloat16 g_A[(size_t)MAXB * KPACK];                   // 4MB
__device__ __align__(256) __nv_bfloat16 g_Bw[(size_t)NHEADS * 2 * IN_DIM * OUT_DIM]; // 16MB

__device__ __forceinline__ uint32_t smem_u32(const void* p) {
    uint32_t a;
    asm("{ .reg .u64 t; cvta.to.shared.u64 t, %1; cvt.u32.u64 %0, t; }"
        : "=r"(a) : "l"(p));
    return a;
}
__device__ __forceinline__ void cpasync16(uint32_t dst, const void* src) {
    asm volatile("cp.async.cg.shared.global [%0], [%1], 16;" :: "r"(dst), "l"(src) : "memory");
}
#define CP_COMMIT() asm volatile("cp.async.commit_group;" ::: "memory")
#define CP_WAIT0()  asm volatile("cp.async.wait_group 0;" ::: "memory")
#define CP_WAIT1()  asm volatile("cp.async.wait_group 1;" ::: "memory")

__device__ __forceinline__ int load_idx(const int* __restrict__ w, int b, int is64) {
    return w[is64 ? (b << 1) : b];
}

// ---------------------------------------------------------------------------
// Kernel 1: prep.
//   bx == 0                : idx dtype sniff + bucket-by-head
//   bx in [1, XB]          : X -> bf16 hi|lo (at original row)
//   bx in (XB, XB+512]     : W -> bf16 hi|lo  [h][sel][k][n]
//   bx in (XB+512, +ZB]    : zero out[0 .. Bn*OUT) (split-K accumulators)
// ---------------------------------------------------------------------------
__global__ __launch_bounds__(256)
void prep(const float* __restrict__ X, const int* __restrict__ idx_w,
          const float* __restrict__ W, float* __restrict__ out, int Bn) {
    const int bx = blockIdx.x;
    const int tid = threadIdx.x;
    const int XB = (Bn + 7) / 8;

    if (bx == 0) {
        __shared__ int s_not;
        __shared__ int s_cnt[NHEADS];
        __shared__ int s_base[NHEADS];
        if (tid == 0) s_not = 0;
        __syncthreads();
        for (int i = tid; i < Bn; i += 256) {
            int v = idx_w[i];
            if (i & 1) { if (v != 0) s_not = 1; }
            else       { if (v < 0 || v >= NHEADS) s_not = 1; }
        }
        __syncthreads();
        const int is64 = s_not ? 0 : 1;
        if (tid == 0) g_is64 = is64;
        if (tid < NHEADS) s_cnt[tid] = 0;
        __syncthreads();
        for (int b = tid; b < Bn; b += 256)
            atomicAdd(&s_cnt[load_idx(idx_w, b, is64) & (NHEADS - 1)], 1);
        __syncthreads();
        if (tid == 0) {
            int acc = 0;
            for (int h = 0; h < NHEADS; h++) { g_off[h] = acc; s_base[h] = acc; acc += s_cnt[h]; }
            g_off[NHEADS] = acc;
        }
        __syncthreads();
        for (int b = tid; b < Bn; b += 256) {
            int h = load_idx(idx_w, b, is64) & (NHEADS - 1);
            g_rows[atomicAdd(&s_base[h], 1)] = b;
        }
    } else if (bx <= XB) {
        int p = (bx - 1) * 8 + (tid >> 5);
        int l = tid & 31;
        if (p >= Bn) return;
        const float4* xr = (const float4*)(X + (size_t)p * IN_DIM);
        union { __nv_bfloat16 h[16]; uint4 u[2]; } hi, lo;
#pragma unroll
        for (int q = 0; q < 4; q++) {
            float4 v = xr[l * 4 + q];
            float f[4] = {v.x, v.y, v.z, v.w};
#pragma unroll
            for (int e = 0; e < 4; e++) {
                __nv_bfloat16 hv = __float2bfloat16(f[e]);
                hi.h[q * 4 + e] = hv;
                lo.h[q * 4 + e] = __float2bfloat16(f[e] - __bfloat162float(hv));
            }
        }
        uint4* dh = (uint4*)(g_A + (size_t)p * KPACK + l * 16);
        dh[0] = hi.u[0]; dh[1] = hi.u[1];
        uint4* dl = (uint4*)(g_A + (size_t)p * KPACK + 512 + l * 16);
        dl[0] = lo.u[0]; dl[1] = lo.u[1];
    } else if (bx <= XB + 512) {
        const int wb = bx - 1 - XB;
        const int total = NHEADS * IN_DIM * (OUT_DIM / 4);
#pragma unroll
        for (int i = 0; i < 8; i++) {
            int id = wb * 2048 + i * 256 + tid;
            if (id >= total) break;
            int h   = id / (IN_DIM * (OUT_DIM / 4));
            int rem = id % (IN_DIM * (OUT_DIM / 4));
            int k   = rem / (OUT_DIM / 4);
            int n4  = rem % (OUT_DIM / 4);
            float4 v = ((const float4*)W)[(size_t)id];
            float f[4] = {v.x, v.y, v.z, v.w};
            union { __nv_bfloat16 h[4]; uint2 u; } hi, lo;
#pragma unroll
            for (int e = 0; e < 4; e++) {
                __nv_bfloat16 hv = __float2bfloat16(f[e]);
                hi.h[e] = hv;
                lo.h[e] = __float2bfloat16(f[e] - __bfloat162float(hv));
            }
            size_t basehi = (((size_t)h * 2 + 0) * IN_DIM + k) * OUT_DIM + n4 * 4;
            size_t baselo = (((size_t)h * 2 + 1) * IN_DIM + k) * OUT_DIM + n4 * 4;
            *(uint2*)(g_Bw + basehi) = hi.u;
            *(uint2*)(g_Bw + baselo) = lo.u;
        }
    } else {
        // zero the matmul region of out (split-K accumulation target)
        const int zb = bx - 1 - XB - 512;
        const long long nf4 = (long long)Bn * OUT_DIM / 4;
        float4 z4 = make_float4(0.f, 0.f, 0.f, 0.f);
#pragma unroll
        for (int i = 0; i < 4; i++) {
            long long id = (long long)zb * 1024 + i * 256 + tid;
            if (id < nf4) ((float4*)out)[id] = z4;
        }
    }
}

// ---------------------------------------------------------------------------
// Kernel 2: grouped GEMM, split-K over 3 bf16 terms, atomicAdd reduction.
// grid (4 n-tiles, ceil(Bn/64) m-slots, 3*NHEADS+1), 128 threads (4 warps).
// Block tile M=64, N=128; warp tile 32x64 (wm = wid&1, wn = wid>>1);
// per-term K: 16 chunks of 32 bf16; 3-stage cp.async, corrected tail drain.
// ---------------------------------------------------------------------------
__global__ __launch_bounds__(128)
void gemm_mma(const float* __restrict__ bias, float* __restrict__ out, int Bn,
              const int* __restrict__ idx_w, float* __restrict__ tail, int mode) {
    const int z = blockIdx.z;
    if (z == 3 * NHEADS) {   // fused tail echo
        if (blockIdx.x == 0 && blockIdx.y == 0 && tail != nullptr) {
            const int is64 = g_is64;
            for (int b = threadIdx.x; b < Bn; b += 128) {
                int v = load_idx(idx_w, b, is64) & (NHEADS - 1);
                if (mode == 1) tail[b] = (float)v;
                else           ((long long*)tail)[b] = (long long)v;
            }
        }
        return;
    }
    const int term = z >> 4;          // 0: hi*hi, 1: lo*hi, 2: hi*lo
    const int h    = z & 15;
    const int n0   = blockIdx.x * 128;
    const int m_begin = g_off[h] + blockIdx.y * 64;
    const int m_end   = g_off[h + 1];
    if (m_begin >= m_end) return;

    __shared__ __align__(16) char sm[3][STAGE_B];

    const int tid  = threadIdx.x;
    const int lane = tid & 31;
    const int wid  = tid >> 5;
    const int wm   = wid & 1;          // 2 warps over M (32 rows each)
    const int wn   = wid >> 1;         // 2 warps over N (64 cols each)

    float acc[2][8][4];
#pragma unroll
    for (int mi = 0; mi < 2; mi++)
#pragma unroll
        for (int ni = 0; ni < 8; ni++)
#pragma unroll
            for (int e = 0; e < 4; e++) acc[mi][ni][e] = 0.0f;

    // Load coordinates: A 64 rows x 4 16B-segs = 256 cps / 128 thr = 2 each;
    //                   B 32 rows x 16 segs    = 512 cps / 128 thr = 4 each.
    const int arow = tid >> 2, aseg = tid & 3;
    const int brow = tid >> 4, bseg = tid & 15;

    const int colbase = (term == 1) ? 512 : 0;   // A hi vs lo half
    const int Bsel    = (term == 2) ? 1 : 0;     // W hi vs lo plane

    const __nv_bfloat16* aSrc[2];
#pragma unroll
    for (int i = 0; i < 2; i++) {
        int p = m_begin + arow + i * 32;
        if (p > Bn - 1) p = Bn - 1;
        aSrc[i] = g_A + (size_t)g_rows[p] * KPACK + colbase + aseg * 8;
    }
    const __nv_bfloat16* bsrcBase =
        g_Bw + (((size_t)h * 2 + Bsel) * IN_DIM) * OUT_DIM + n0 + bseg * 8;

    auto load_chunk = [&](int c, int stg) {
        const int kk = c << 5;
        const uint32_t aB = smem_u32(&sm[stg][0]);
        const uint32_t bB = aB + A_TILE_B;
#pragma unroll
        for (int i = 0; i < 2; i++)
            cpasync16(aB + (arow + i * 32) * A_STRIDE_B + aseg * 16, aSrc[i] + kk);
#pragma unroll
        for (int i = 0; i < 4; i++) {
            int r = brow + i * 8;
            cpasync16(bB + r * B_STRIDE_B + bseg * 16,
                      bsrcBase + (size_t)(kk + r) * OUT_DIM);
        }
        CP_COMMIT();
    };

    load_chunk(0, 0);
    load_chunk(1, 1);

    for (int c = 0; c < NCHUNK_T; c++) {
        if (c + 1 < NCHUNK_T) CP_WAIT1();   // pending {c,c+1} -> drains c
        else                  CP_WAIT0();   // last chunk: full drain (fixes R9 race)
        __syncthreads();                    // orders prior reads before reuse below

        if (c + 2 < NCHUNK_T) load_chunk(c + 2, (c + 2) % 3);

        const int stg = c % 3;
        const uint32_t aB = smem_u32(&sm[stg][0]);
        const uint32_t bB = aB + A_TILE_B;

#pragma unroll
        for (int km = 0; km < 32; km += 16) {
            uint32_t a[2][4];
#pragma unroll
            for (int mi = 0; mi < 2; mi++) {
                int row = wm * 32 + mi * 16 + (lane & 15);
                uint32_t addr = aB + row * A_STRIDE_B + km * 2 + ((lane >> 4) & 1) * 16;
                asm volatile("ldmatrix.sync.aligned.m8n8.x4.shared.b16 {%0,%1,%2,%3}, [%4];"
                    : "=r"(a[mi][0]), "=r"(a[mi][1]), "=r"(a[mi][2]), "=r"(a[mi][3])
                    : "r"(addr));
            }
            uint32_t b[8][2];
#pragma unroll
            for (int g = 0; g < 4; g++) {
                int krow = km + (lane & 7) + ((lane >> 3) & 1) * 8;
                int ncol = wn * 64 + g * 16 + ((lane >> 4) & 1) * 8;
                uint32_t addr = bB + krow * B_STRIDE_B + ncol * 2;
                asm volatile("ldmatrix.sync.aligned.m8n8.x4.trans.shared.b16 {%0,%1,%2,%3}, [%4];"
                    : "=r"(b[g * 2][0]), "=r"(b[g * 2][1]),
                      "=r"(b[g * 2 + 1][0]), "=r"(b[g * 2 + 1][1])
                    : "r"(addr));
            }
#pragma unroll
            for (int mi = 0; mi < 2; mi++)
#pragma unroll
                for (int ni = 0; ni < 8; ni++) {
                    asm volatile(
                        "mma.sync.aligned.m16n8k16.row.col.f32.bf16.bf16.f32 "
                        "{%0,%1,%2,%3}, {%4,%5,%6,%7}, {%8,%9}, {%0,%1,%2,%3};"
                        : "+f"(acc[mi][ni][0]), "+f"(acc[mi][ni][1]),
                          "+f"(acc[mi][ni][2]), "+f"(acc[mi][ni][3])
                        : "r"(a[mi][0]), "r"(a[mi][1]), "r"(a[mi][2]), "r"(a[mi][3]),
                          "r"(b[ni][0]), "r"(b[ni][1]));
                }
        }
    }

    // Epilogue: atomicAdd partial sums into out (zeroed by prep).
    // term 0 also adds bias (exactly once per output element).
#pragma unroll
    for (int mi = 0; mi < 2; mi++) {
#pragma unroll
        for (int rp = 0; rp < 2; rp++) {
            int r = wm * 32 + mi * 16 + rp * 8 + (lane >> 2);
            int p = m_begin + r;
            if (p < m_end) {
                int bb = g_rows[p];
                float* op = out + (size_t)bb * OUT_DIM + n0 + wn * 64 + (lane & 3) * 2;
                const float* bp = bias + h * OUT_DIM + n0 + wn * 64 + (lane & 3) * 2;
#pragma unroll
                for (int ni = 0; ni < 8; ni++) {
                    float v0 = acc[mi][ni][rp * 2 + 0];
                    float v1 = acc[mi][ni][rp * 2 + 1];
                    if (term == 0) { v0 += bp[ni * 8 + 0]; v1 += bp[ni * 8 + 1]; }
                    atomicAdd(op + ni * 8 + 0, v0);
                    atomicAdd(op + ni * 8 + 1, v1);
                }
            }
        }
    }
}

extern "C" void kernel_launch(void* const* d_in, const int* in_sizes, int n_in,
                              void* d_out, int out_size) {
    const float* X     = (const float*)d_in[0];
    const int*   idx_w = (const int*)d_in[1];
    const float* W     = (const float*)d_in[2];
    const float* bias  = (const float*)d_in[3];
    float*       out   = (float*)d_out;

    const int Bn = in_sizes[1];

    const int XB = (Bn + 7) / 8;
    const int ZB = (int)(((long long)Bn * OUT_DIM / 4 + 1023) / 1024);
    prep<<<1 + XB + 512 + ZB, 256>>>(X, idx_w, W, out, Bn);

    long long extra = (long long)out_size - (long long)Bn * OUT_DIM;
    float* tail = nullptr;
    int mode = 0;
    if (extra >= Bn) {
        mode = (extra >= 2 * (long long)Bn) ? 2 : 1;
        tail = out + (size_t)Bn * OUT_DIM;
    }

    int m_slots = (Bn + 63) / 64;
    dim3 g(OUT_DIM / 128, m_slots, 3 * NHEADS + 1);
    gemm_mma<<<g, 128>>>(bias, out, Bn, idx_w, tail, mode);
}